// round 1
// baseline (speedup 1.0000x reference)
#include <cuda_runtime.h>
#include <cstdint>

#define ETHREADS 256

__device__ double g_acc;
__device__ __align__(16) float g_W2r[16 * 32];

// ---------------------------------------------------------------------------
// prep: reduce W2 (16,256) over the trailing v' dim -> W2r (16,32),
// folding in sqrt(2) (post-relu scale) and 1/sqrt(HID)=0.25. Also zero g_acc.
// ---------------------------------------------------------------------------
__global__ void prep_kernel(const float* __restrict__ W2) {
    int tid = blockIdx.x * blockDim.x + threadIdx.x;
    if (tid == 0) g_acc = 0.0;
    if (tid < 512) {
        int c = tid >> 5;   // hid 0..15
        int o = tid & 31;   // (k*8+u) 0..31
        const float* p = W2 + c * 256 + o * 8;
        float s = 0.f;
#pragma unroll
        for (int v = 0; v < 8; v++) s += p[v];
        g_W2r[c * 32 + o] = s * 0.35355339059327373f;  // 0.25*sqrt(2)
    }
}

__device__ __forceinline__ void fma2(unsigned long long& d, unsigned long long a,
                                     unsigned long long b) {
    asm("fma.rn.f32x2 %0, %1, %2, %0;" : "+l"(d) : "l"(a), "l"(b));
}
__device__ __forceinline__ unsigned long long pack2(float lo, float hi) {
    unsigned long long r;
    asm("mov.b64 %0, {%1, %2};" : "=l"(r) : "f"(lo), "f"(hi));
    return r;
}
__device__ __forceinline__ float2 unpack2(unsigned long long v) {
    float2 f;
    asm("mov.b64 {%0, %1}, %2;" : "=f"(f.x), "=f"(f.y) : "l"(v));
    return f;
}

// ---------------------------------------------------------------------------
// main: one thread per edge, computes the edge's total contribution to the
// final scalar, reduces warp->block->double atomicAdd.
// ---------------------------------------------------------------------------
__global__ void __launch_bounds__(ETHREADS)
edge_kernel(const float* __restrict__ feat, const float* __restrict__ evec,
            const float* __restrict__ W1, const int* __restrict__ esrc, int E) {
    __shared__ __align__(16) float sW2r[512];
    __shared__ float sW1[160];
    __shared__ float sred[ETHREADS / 32];

    for (int i = threadIdx.x; i < 512; i += blockDim.x) sW2r[i] = g_W2r[i];
    for (int i = threadIdx.x; i < 160; i += blockDim.x) sW1[i] = W1[i];
    __syncthreads();

    float contrib = 0.f;
    int e = blockIdx.x * blockDim.x + threadIdx.x;
    if (e < E) {
        float ex = evec[3 * e + 0], ey = evec[3 * e + 1], ez = evec[3 * e + 2];
        float r = sqrtf(ex * ex + ey * ey + ez * ez);
        float inv_r = 1.0f / r;
        const float SQ3 = 1.7320508075688772f;
        float s1x = SQ3 * ex * inv_r;
        float s1y = SQ3 * ey * inv_r;
        float s1z = SQ3 * ez * inv_r;

        // radial basis: centers at (j+1)*step, step = 3/11; only two bases
        // (j = floor(t)-1, floor(t)) can be nonzero for a given r.
        const float inv_step = 11.0f / 3.0f;
        float t = r * inv_step;
        int jb = (int)floorf(t);
        int ja = jb - 1;
        float fa = 0.f, fb = 0.f;
        bool va = (ja >= 0) && (ja <= 9);
        bool vb = (jb >= 0) && (jb <= 9);
        if (va) {
            float diff = t - (float)(ja + 1);
            float den = 1.0f - diff * diff;
            if (den > 0.f) fa = 1.14136f * __expf(2.0f - 2.0f / den);
        }
        if (vb) {
            float diff = t - (float)(jb + 1);
            float den = 1.0f - diff * diff;
            if (den > 0.f) fb = 1.14136f * __expf(2.0f - 2.0f / den);
        }
        int ja_c = va ? ja : 0;
        int jb_c = vb ? jb : 0;

        // h = relu(f @ W1)   (sqrt(10) scales cancel exactly)
        float h[16];
#pragma unroll
        for (int c = 0; c < 16; c++) {
            float v = fa * sW1[ja_c * 16 + c] + fb * sW1[jb_c * 16 + c];
            h[c] = fmaxf(v, 0.f);
        }

        // wsum = h @ W2r : 16x32 matvec as packed f32x2 FFMA2
        unsigned long long acc[16];
#pragma unroll
        for (int j = 0; j < 16; j++) acc[j] = 0ULL;
#pragma unroll
        for (int c = 0; c < 16; c++) {
            unsigned long long hc2 = pack2(h[c], h[c]);
            const ulonglong2* row = (const ulonglong2*)(sW2r + c * 32);
#pragma unroll
            for (int o = 0; o < 8; o++) {
                ulonglong2 p = row[o];
                fma2(acc[2 * o + 0], hc2, p.x);
                fma2(acc[2 * o + 1], hc2, p.y);
            }
        }
        float ws[32];
#pragma unroll
        for (int j = 0; j < 16; j++) {
            float2 f = unpack2(acc[j]);
            ws[2 * j] = f.x;
            ws[2 * j + 1] = f.y;
        }

        // gather node features (128B, L2-resident)
        const float4* xp = (const float4*)(feat + (size_t)esrc[e] * 32);
        float x[32];
#pragma unroll
        for (int q = 0; q < 8; q++) {
            float4 v4 = xp[q];
            x[4 * q + 0] = v4.x;
            x[4 * q + 1] = v4.y;
            x[4 * q + 2] = v4.z;
            x[4 * q + 3] = v4.w;
        }

        float A = 0.f, B = 0.f, C = 0.f, D = 0.f;
#pragma unroll
        for (int u = 0; u < 8; u++) {
            float su = x[u];
            float v0 = x[8 + 3 * u], v1 = x[9 + 3 * u], v2 = x[10 + 3 * u];
            float vdot = v0 * s1x + v1 * s1y + v2 * s1z;
            float vsum = v0 + v1 + v2;
            A += su * ws[u];
            B += vdot * ws[8 + u];
            C += su * ws[16 + u];
            D += vsum * ws[24 + u];
        }
        float S1 = s1x + s1y + s1z;
        contrib = A + 0.5773502691896258f * B + S1 * C + D;
    }

    // warp reduce
#pragma unroll
    for (int off = 16; off > 0; off >>= 1)
        contrib += __shfl_down_sync(0xffffffffu, contrib, off);
    int lane = threadIdx.x & 31;
    int warp = threadIdx.x >> 5;
    if (lane == 0) sred[warp] = contrib;
    __syncthreads();
    if (warp == 0) {
        float v = (lane < (ETHREADS / 32)) ? sred[lane] : 0.f;
#pragma unroll
        for (int off = 16; off > 0; off >>= 1)
            v += __shfl_down_sync(0xffffffffu, v, off);
        if (lane == 0) atomicAdd(&g_acc, (double)v);
    }
}

// ---------------------------------------------------------------------------
// finish: apply the global scale 0.25 (pw prefactors) * 0.25 (1/sqrt(16))
// ---------------------------------------------------------------------------
__global__ void finish_kernel(float* out) { out[0] = (float)(g_acc * 0.0625); }

extern "C" void kernel_launch(void* const* d_in, const int* in_sizes, int n_in,
                              void* d_out, int out_size) {
    const float* feat = (const float*)d_in[0];  // input_features (N, 32)
    const float* evec = (const float*)d_in[1];  // edge_vec (E, 3)
    const float* W1   = (const float*)d_in[2];  // (10, 16)
    const float* W2   = (const float*)d_in[3];  // (16, 256)
    const int*   esrc = (const int*)d_in[4];    // (E,)
    // d_in[5] = edge_dst, d_in[6] = num_nodes: algebraically irrelevant to the
    // final scalar (segment_sum followed by total sum == sum over edges).
    int E = in_sizes[4];

    prep_kernel<<<2, 256>>>(W2);
    int blocks = (E + ETHREADS - 1) / ETHREADS;
    edge_kernel<<<blocks, ETHREADS>>>(feat, evec, W1, esrc, E);
    finish_kernel<<<1, 1>>>((float*)d_out);
}